// round 7
// baseline (speedup 1.0000x reference)
#include <cuda_runtime.h>

#define N_FULL   50000
#define NLAT     10
#define MU       32
#define BATCH    8
#define NODES    32
#define MSTR     33               // m-stride in G/W2
#define ISTR     1058             // i-stride = 32*33+2 (mod 32 == 2)
#define GSZ      (NLAT * ISTR)    // 10580 floats per array
#define TMAIN    768

// Scratch (static __device__ arrays: no dynamic allocation allowed)
__device__ float g_encoded[BATCH * NLAT];                 // bias pre-added
__device__ __align__(128) float g_dec4[N_FULL * 16];      // 64B rows [v0..v9,pad6]

// ---------------------------------------------------------------------------
// Kernel 1 (fused): blocks 0..79 compute encoded[b,i] + enc_b[i] directly.
// Blocks 80..275 transpose decoder [n,N] -> [N,16] (64B-aligned rows).
// ---------------------------------------------------------------------------
__global__ void __launch_bounds__(256)
prep_encode_kernel(const float* __restrict__ x,
                   const float* __restrict__ ew,
                   const float* __restrict__ enc_b,
                   const float* __restrict__ decoder) {
    if (blockIdx.x < BATCH * NLAT) {
        const int b = blockIdx.x / NLAT;
        const int i = blockIdx.x % NLAT;
        const float4* xr = (const float4*)(x  + (size_t)b * N_FULL);
        const float4* wr = (const float4*)(ew + (size_t)i * N_FULL);
        float acc = 0.0f;
        for (int t = threadIdx.x; t < N_FULL / 4; t += 256) {
            float4 a = __ldg(xr + t);
            float4 c = __ldg(wr + t);
            acc = fmaf(a.x, c.x, acc);
            acc = fmaf(a.y, c.y, acc);
            acc = fmaf(a.z, c.z, acc);
            acc = fmaf(a.w, c.w, acc);
        }
#pragma unroll
        for (int d = 16; d > 0; d >>= 1)
            acc += __shfl_xor_sync(0xffffffffu, acc, d);
        __shared__ float red[8];
        int lane = threadIdx.x & 31, warp = threadIdx.x >> 5;
        if (lane == 0) red[warp] = acc;
        __syncthreads();
        if (threadIdx.x == 0) {
            float s = 0.0f;
#pragma unroll
            for (int w = 0; w < 8; w++) s += red[w];
            g_encoded[blockIdx.x] = s + __ldg(enc_b + i);   // bias folded in
        }
    } else {
        int p = (blockIdx.x - BATCH * NLAT) * 256 + threadIdx.x;
        if (p < N_FULL) {
            float v[NLAT];
#pragma unroll
            for (int i = 0; i < NLAT; i++)
                v[i] = __ldg(decoder + (size_t)i * N_FULL + p);
            float4* dst = (float4*)(g_dec4 + (size_t)p * 16);
            dst[0] = make_float4(v[0], v[1], v[2], v[3]);
            dst[1] = make_float4(v[4], v[5], v[6], v[7]);
            dst[2] = make_float4(v[8], v[9], 0.0f, 0.0f);
            dst[3] = make_float4(0.0f, 0.0f, 0.0f, 0.0f);
        }
    }
}

// ---------------------------------------------------------------------------
// Kernel 2: main. 768 threads (24 warps), 32 nodes/block, single i-pass.
// 88.8KB smem/CTA -> 2 CTAs/SM, 48 warps/SM (~75% occupancy).
//
//  Phase A (gather): 128 chunks of 8 rows grid-strided over 24 warps; 4
//    lanes per 64B decoder row (q=0..2 carry the 10 values): one warp-LDG
//    touches 8 random rows = 8 lines -> 1 L1 wavefront per neighbour row.
//    Scatter banks (8q+2u+m+j)%32: conflict-free.
//  Phase B (scan): warps 0..9, task (i=warp, j=lane): G <- prefix(g),
//    W2 <- prefix(m^2 g) over m. Banks (2i+m+j)%32: conflict-free.
//  Phase C: warp = (b, third), lane = j over 32 consecutive nodes (bw loads
//    128B-coalesced). Thirds cover i {0-3},{4-6},{7-9}; closed-form window:
//      smoothed = (Pg[cnt-1] - inv2*Pm2[cnt-1]) / (cnt - inv2*S2(cnt)).
//    Partials combined through smem P[2][8][33].
// ---------------------------------------------------------------------------
__global__ void __launch_bounds__(TMAIN, 2)
main_kernel(const float* __restrict__ bw,
            const int*   __restrict__ neigh,
            float*       __restrict__ out) {
    extern __shared__ float sm[];
    float*          G  = sm;                       // [GSZ]
    float*          W2 = sm + GSZ;                 // [GSZ]
    float*          P  = sm + 2 * GSZ;             // [2][8][33] third-partials
    unsigned short* NB = (unsigned short*)(sm + 2 * GSZ + 2 * BATCH * MSTR);

    const int tid    = threadIdx.x;
    const int lane   = tid & 31;
    const int warp   = tid >> 5;
    const int p_base = blockIdx.x * NODES;

    // ---- neighbour tile (input-only: load before PDL sync) ----
    if (tid < 512) {
        int base = p_base * MU + tid * 2;
        int2 v = make_int2(0, 0);
        if (base + 1 < N_FULL * MU) v = *(const int2*)(neigh + base);
        NB[tid * 2 + 0] = (unsigned short)v.x;
        NB[tid * 2 + 1] = (unsigned short)v.y;
    }
#if defined(__CUDA_ARCH__) && (__CUDA_ARCH__ >= 900)
    cudaGridDependencySynchronize();   // wait for prep_encode results
#endif
    __syncthreads();

    // ---- Phase A: cooperative gather (chunks of 8 rows over 24 warps) ----
    {
        const int q  = lane & 3;       // 16B quarter of the 64B row
        const int rl = lane >> 2;      // row-in-instruction 0..7
        for (int c = warp; c < 128; c += 24) {
            const int r = c * 8 + rl;              // flat row: j=r>>5, m=r&31
            const int m = r & 31;
            const int j = r >> 5;
            const int nb = NB[r];
            if (q < 3) {
                float4 v = __ldg((const float4*)g_dec4 + nb * 4 + q);
                const int a0 = (4 * q) * ISTR + m * MSTR + j;
                G[a0] = v.x;
                G[a0 + ISTR] = v.y;
                if (q < 2) {
                    G[a0 + 2 * ISTR] = v.z;
                    G[a0 + 3 * ISTR] = v.w;
                }
            }
        }
    }
    __syncthreads();

    // ---- Phase B: inclusive prefix over m (warps 0..9: i = warp, j = lane)
    if (tid < NLAT * NODES) {
        const int base = warp * ISTR + lane;
        float pg = 0.0f, pm = 0.0f;
#pragma unroll
        for (int m = 0; m < MU; m++) {
            float v = G[base + m * MSTR];
            pg += v;
            pm = fmaf((float)(m * m), v, pm);
            G [base + m * MSTR] = pg;
            W2[base + m * MSTR] = pm;
        }
    }
    __syncthreads();

    // ---- Phase C: warp = (b, third); lane = j over 32 nodes ----
    const int b  = warp >> 2 | 0;       // computed below properly
    const int wb = warp / 3;            // batch 0..7
    const int it = warp - wb * 3;       // third 0..2
    const int j  = lane;
    const int p  = p_base + j;
    const int pc = (p < N_FULL) ? p : (N_FULL - 1);
    (void)b;

    const int istart = (it == 0) ? 0 : (it == 1) ? 4 : 7;
    const int iend   = (it == 0) ? 4 : (it == 1) ? 7 : 10;

    float encb[NLAT];
#pragma unroll
    for (int k = 0; k < NLAT; k++)
        encb[k] = g_encoded[wb * NLAT + k];        // bias already included

    const float* bwp = bw + pc;
    float acc = 0.0f;
    for (int i = istart; i < iend; i++) {
        float z = 0.0f;
        const float* row = bwp + (size_t)(i * NLAT) * N_FULL;
#pragma unroll
        for (int k = 0; k < NLAT; k++)
            z = fmaf(encb[k], __ldg(row + (size_t)k * N_FULL), z);

        float e    = __expf(-z);
        float tt   = 1.0f + e;                              // = 1/w
        float u    = __fdividef((float)MU, tt);             // = MU*w
        int   cnt  = min(MU, (int)u + 1);                   // #active m
        float inv2 = tt * tt * (1.0f / (float)(MU * MU));   // 1/(MU*w)^2

        const int base = i * ISTR + (cnt - 1) * MSTR + j;
        float Pg = G[base];
        float Pm = W2[base];
        int   c1 = cnt - 1;
        float S2 = (float)(c1 * cnt * (2 * cnt - 1)) * (1.0f / 6.0f);
        float s  = (float)cnt - inv2 * S2;
        float smv = __fdividef(fmaf(-inv2, Pm, Pg), s);
        acc = fmaf(encb[i], smv, acc);
    }

    // combine the three thirds through smem
    if (it != 0) P[(it - 1) * (BATCH * MSTR) + wb * MSTR + j] = acc;
    __syncthreads();
    if (it == 0 && p < N_FULL)
        out[(size_t)wb * N_FULL + p] =
            acc + P[wb * MSTR + j] + P[BATCH * MSTR + wb * MSTR + j];
}

// ---------------------------------------------------------------------------
extern "C" void kernel_launch(void* const* d_in, const int* in_sizes, int n_in,
                              void* d_out, int out_size) {
    const float* x       = (const float*)d_in[0];
    const float* enc_w   = (const float*)d_in[1];
    const float* enc_b   = (const float*)d_in[2];
    const float* decoder = (const float*)d_in[3];
    const float* bw      = (const float*)d_in[4];
    const int*   neigh   = (const int*)  d_in[5];
    float*       out     = (float*)d_out;
    (void)in_sizes; (void)n_in; (void)out_size;

    const int tp_blocks = (N_FULL + 255) / 256;                 // 196
    prep_encode_kernel<<<BATCH * NLAT + tp_blocks, 256>>>(x, enc_w, enc_b,
                                                          decoder);

    size_t smem_bytes = (size_t)(2 * GSZ + 2 * BATCH * MSTR) * sizeof(float)
                      + (size_t)(NODES * MU) * sizeof(unsigned short);
    cudaFuncSetAttribute(main_kernel,
                         cudaFuncAttributeMaxDynamicSharedMemorySize,
                         (int)smem_bytes);

    // main with PDL: overlap its prologue with prep_encode execution
    cudaLaunchConfig_t cfg = {};
    cfg.gridDim  = dim3((N_FULL + NODES - 1) / NODES);   // 1563
    cfg.blockDim = dim3(TMAIN);
    cfg.dynamicSmemBytes = smem_bytes;
    cfg.stream = 0;
    cudaLaunchAttribute attr[1];
    attr[0].id = cudaLaunchAttributeProgrammaticStreamSerialization;
    attr[0].val.programmaticStreamSerializationAllowed = 1;
    cfg.attrs = attr;
    cfg.numAttrs = 1;
    if (cudaLaunchKernelEx(&cfg, main_kernel, bw, neigh, out) != cudaSuccess) {
        main_kernel<<<(N_FULL + NODES - 1) / NODES, TMAIN, smem_bytes>>>(
            bw, neigh, out);
    }
}